// round 1
// baseline (speedup 1.0000x reference)
#include <cuda_runtime.h>
#include <cstdint>
#include <math.h>

// Problem sizes
#define NN   8192      // nodes
#define MM   4096      // hyperedges
#define FIN  256
#define DD   128
#define CAPN 64        // max edges per node  (Binomial(4096,.005): mean 20.5, sd 4.5)
#define CAPE 128       // max nodes per edge  (Binomial(8192,.005): mean 41.0, sd 6.4)

// ---------------- device scratch (static: no allocations allowed) ----------------
__device__ float g_v1[FIN];          // weight2 @ a[D:]
__device__ float g_v2[FIN];          // weight2 @ a2[:D]
__device__ float g_w3v[DD];          // weight3 @ a2[D:]
__device__ float g_c;                // word_context . a[:D]
__device__ float g_xt[NN * DD];      // x @ weight
__device__ float g_s1[NN];           // leaky(c + x.v1)
__device__ float g_n2[NN];           // x.v2
__device__ int   g_node_cnt[NN];
__device__ int   g_node_idx[NN * CAPN];
__device__ int   g_edge_cnt[MM];
__device__ int   g_edge_idx[MM * CAPE];
__device__ float g_edge[MM * DD];
__device__ float g_e2[MM];

// ---------------- helpers ----------------
__device__ __forceinline__ float blockReduceSum128(float v, float* red) {
    int lane = threadIdx.x & 31, wid = threadIdx.x >> 5;
    #pragma unroll
    for (int o = 16; o > 0; o >>= 1) v += __shfl_xor_sync(0xffffffffu, v, o);
    if (lane == 0) red[wid] = v;
    __syncthreads();
    float r = red[0] + red[1] + red[2] + red[3];
    __syncthreads();
    return r;
}
__device__ __forceinline__ float blockReduceMax128(float v, float* red) {
    int lane = threadIdx.x & 31, wid = threadIdx.x >> 5;
    #pragma unroll
    for (int o = 16; o > 0; o >>= 1) v = fmaxf(v, __shfl_xor_sync(0xffffffffu, v, o));
    if (lane == 0) red[wid] = v;
    __syncthreads();
    float r = fmaxf(fmaxf(red[0], red[1]), fmaxf(red[2], red[3]));
    __syncthreads();
    return r;
}

// ---------------- K-zero: reset edge counters (graph replays reuse globals) ------
__global__ void k_zero() {
    int i = blockIdx.x * blockDim.x + threadIdx.x;
    if (i < MM) g_edge_cnt[i] = 0;
}

// ---------------- K0: tiny precomputes -------------------------------------------
__global__ void k0(const float* __restrict__ W2, const float* __restrict__ W3,
                   const float* __restrict__ wc, const float* __restrict__ a,
                   const float* __restrict__ a2) {
    int t = threadIdx.x;
    if (t < FIN) {
        float s1 = 0.f, s2 = 0.f;
        #pragma unroll 4
        for (int c = 0; c < DD; c++) {
            float w = W2[t * DD + c];
            s1 += w * a[DD + c];
            s2 += w * a2[c];
        }
        g_v1[t] = s1; g_v2[t] = s2;
    }
    if (t < DD) {
        float s = 0.f;
        #pragma unroll 4
        for (int c = 0; c < DD; c++) s += W3[t * DD + c] * a2[DD + c];
        g_w3v[t] = s;
    }
    if (t == 0) {
        float s = 0.f;
        for (int c = 0; c < DD; c++) s += wc[c] * a[c];
        g_c = s;
    }
}

// ---------------- K1: xt = x @ weight, fp32x2 packed FMA --------------------------
// block: 128 threads (one output column each), 16 rows per block.
__global__ void __launch_bounds__(128) k1(const float* __restrict__ x,
                                          const float* __restrict__ W) {
    __shared__ float2 xs[FIN][9];   // xs[k][p] = (x[r0+2p][k], x[r0+2p+1][k]); padded stride
    int t = threadIdx.x;
    int r0 = blockIdx.x * 16;

    for (int i = t; i < 16 * FIN; i += 128) {
        int r = i >> 8;          // 0..15
        int k = i & (FIN - 1);   // 0..255
        float v = x[(size_t)(r0 + r) * FIN + k];
        reinterpret_cast<float*>(&xs[k][r >> 1])[r & 1] = v;
    }
    __syncthreads();

    unsigned long long acc[8];
    #pragma unroll
    for (int p = 0; p < 8; p++) acc[p] = 0ull;

    const float* Wc = W + t;
    #pragma unroll 4
    for (int k = 0; k < FIN; k++) {
        float w = Wc[(size_t)k * DD];
        unsigned wu = __float_as_uint(w);
        unsigned long long bb;
        asm("mov.b64 %0, {%1, %1};" : "=l"(bb) : "r"(wu));
        #pragma unroll
        for (int p = 0; p < 8; p++) {
            unsigned long long xp = *reinterpret_cast<const unsigned long long*>(&xs[k][p]);
            asm("fma.rn.f32x2 %0, %1, %2, %0;" : "+l"(acc[p]) : "l"(xp), "l"(bb));
        }
    }

    #pragma unroll
    for (int p = 0; p < 8; p++) {
        unsigned lo, hi;
        asm("mov.b64 {%0, %1}, %2;" : "=r"(lo), "=r"(hi) : "l"(acc[p]));
        g_xt[(size_t)(r0 + 2 * p) * DD + t]     = __uint_as_float(lo);
        g_xt[(size_t)(r0 + 2 * p + 1) * DD + t] = __uint_as_float(hi);
    }
}

// ---------------- K1b: s1[j], n2[j] (one warp per node row) -----------------------
__global__ void __launch_bounds__(256) k1b(const float* __restrict__ x) {
    int gw = (blockIdx.x * 256 + threadIdx.x) >> 5;
    int lane = threadIdx.x & 31;
    if (gw >= NN) return;
    const float* xr = x + (size_t)gw * FIN;
    float a1 = 0.f, a2v = 0.f;
    #pragma unroll
    for (int k = lane; k < FIN; k += 32) {
        float v = xr[k];
        a1  += v * g_v1[k];
        a2v += v * g_v2[k];
    }
    #pragma unroll
    for (int o = 16; o > 0; o >>= 1) {
        a1  += __shfl_down_sync(0xffffffffu, a1, o);
        a2v += __shfl_down_sync(0xffffffffu, a2v, o);
    }
    if (lane == 0) {
        float s = g_c + a1;
        g_s1[gw] = (s > 0.f) ? s : 0.2f * s;
        g_n2[gw] = a2v;
    }
}

// ---------------- K2: single pass over adj -> both sparse structures --------------
// one warp per node row; deterministic in-row order for node lists,
// atomic-append (sorted later) for edge lists.
__global__ void __launch_bounds__(256) k2(const float* __restrict__ adj) {
    int gw = (blockIdx.x * 256 + threadIdx.x) >> 5;
    int lane = threadIdx.x & 31;
    if (gw >= NN) return;
    const float4* row = reinterpret_cast<const float4*>(adj + (size_t)gw * MM);
    int* nrow = g_node_idx + (size_t)gw * CAPN;
    int base = 0;
    for (int c = 0; c < 32; c++) {                 // 32 chunks * 128 cols
        float4 v = row[c * 32 + lane];
        int m0 = c * 128 + lane * 4;
        float vals[4] = {v.x, v.y, v.z, v.w};
        int cnt = (v.x > 0.f) + (v.y > 0.f) + (v.z > 0.f) + (v.w > 0.f);
        // inclusive scan of per-lane counts
        int pref = cnt;
        #pragma unroll
        for (int o = 1; o < 32; o <<= 1) {
            int n = __shfl_up_sync(0xffffffffu, pref, o);
            if (lane >= o) pref += n;
        }
        int total = __shfl_sync(0xffffffffu, pref, 31);
        int pos = base + pref - cnt;
        #pragma unroll
        for (int q = 0; q < 4; q++) {
            if (vals[q] > 0.f) {
                if (pos < CAPN) nrow[pos] = m0 + q;
                pos++;
                int m = m0 + q;
                int slot = atomicAdd(&g_edge_cnt[m], 1);
                if (slot < CAPE) g_edge_idx[(size_t)m * CAPE + slot] = gw;
            }
        }
        base += total;
    }
    if (lane == 0) g_node_cnt[gw] = base;
}

// ---------------- K2b: bitonic-sort each edge's node list (determinism+locality) --
__global__ void __launch_bounds__(CAPE) k2b() {
    __shared__ int s[CAPE];
    int m = blockIdx.x, t = threadIdx.x;
    int cnt = min(g_edge_cnt[m], CAPE);
    s[t] = (t < cnt) ? g_edge_idx[(size_t)m * CAPE + t] : 0x7fffffff;
    __syncthreads();
    for (int k = 2; k <= CAPE; k <<= 1) {
        for (int j = k >> 1; j > 0; j >>= 1) {
            int ixj = t ^ j;
            if (ixj > t) {
                int a = s[t], b = s[ixj];
                bool asc = ((t & k) == 0);
                if ((a > b) == asc) { s[t] = b; s[ixj] = a; }
            }
            __syncthreads();
        }
    }
    if (t < cnt) g_edge_idx[(size_t)m * CAPE + t] = s[t];
    if (t == 0)  g_edge_cnt[m] = cnt;
}

// ---------------- K3: per-edge softmax + aggregate xt; also e2 --------------------
__global__ void __launch_bounds__(128) k3() {
    __shared__ int   li[CAPE];
    __shared__ float w[CAPE];
    __shared__ float red[4];
    int m = blockIdx.x, t = threadIdx.x;
    int cnt = g_edge_cnt[m];
    if (t < cnt) li[t] = g_edge_idx[(size_t)m * CAPE + t];
    __syncthreads();
    float sv = (t < cnt) ? g_s1[li[t]] : -INFINITY;
    float mx = blockReduceMax128(sv, red);
    float e = (t < cnt) ? __expf(sv - mx) : 0.f;
    w[t] = e;
    float sum = blockReduceSum128(e, red);
    __syncthreads();

    float acc = 0.f;
    for (int i = 0; i < cnt; i++)
        acc += w[i] * g_xt[(size_t)li[i] * DD + t];
    float val = (cnt > 0) ? acc / sum : 0.f;
    g_edge[(size_t)m * DD + t] = val;

    float e2 = blockReduceSum128(val * g_w3v[t], red);
    if (t == 0) g_e2[m] = e2;
}

// ---------------- K5: per-node softmax + aggregate edge; ELU ----------------------
__global__ void __launch_bounds__(128) k5(float* __restrict__ out) {
    __shared__ int   li[CAPN];
    __shared__ float w[CAPN];
    __shared__ float red[4];
    int j = blockIdx.x, t = threadIdx.x;
    int cnt = min(g_node_cnt[j], CAPN);
    if (t < cnt) li[t] = g_node_idx[(size_t)j * CAPN + t];
    __syncthreads();
    float n2 = g_n2[j];
    float sv = -INFINITY;
    if (t < cnt) {
        float s = g_e2[li[t]] + n2;
        sv = (s > 0.f) ? s : 0.2f * s;     // leaky on (e2_i + n2_j)
    }
    float mx = blockReduceMax128(sv, red);
    float e = (t < cnt) ? __expf(sv - mx) : 0.f;
    if (t < CAPN) w[t] = e;
    float sum = blockReduceSum128(e, red);
    __syncthreads();

    float acc = 0.f;
    for (int i = 0; i < cnt; i++)
        acc += w[i] * g_edge[(size_t)li[i] * DD + t];
    float val = (cnt > 0) ? acc / sum : 0.f;
    out[(size_t)j * DD + t] = (val > 0.f) ? val : (__expf(val) - 1.f);
}

// ---------------- launch ----------------------------------------------------------
extern "C" void kernel_launch(void* const* d_in, const int* in_sizes, int n_in,
                              void* d_out, int out_size) {
    const float* x   = (const float*)d_in[0];   // [8192,256]
    const float* adj = (const float*)d_in[1];   // [8192,4096]
    const float* W   = (const float*)d_in[2];   // [256,128]
    const float* W2  = (const float*)d_in[3];   // [256,128]
    const float* W3  = (const float*)d_in[4];   // [128,128]
    const float* wc  = (const float*)d_in[5];   // [1,128]
    const float* a   = (const float*)d_in[6];   // [256,1]
    const float* a2  = (const float*)d_in[7];   // [256,1]
    float* out = (float*)d_out;                 // [8192,128]

    k_zero<<<4, 1024>>>();
    k0<<<1, 256>>>(W2, W3, wc, a, a2);
    k1<<<NN / 16, 128>>>(x, W);
    k1b<<<NN / 8, 256>>>(x);
    k2<<<NN / 8, 256>>>(adj);
    k2b<<<MM, CAPE>>>();
    k3<<<MM, 128>>>();
    k5<<<NN, 128>>>(out);
}

// round 2
// speedup vs baseline: 1.2052x; 1.2052x over previous
#include <cuda_runtime.h>
#include <cstdint>
#include <math.h>

// Problem sizes
#define NN   8192      // nodes
#define MM   4096      // hyperedges
#define FIN  256
#define DD   128
#define CAPN 64        // max edges per node  (Binomial(4096,.005): mean 20.5, sd 4.5)
#define CAPE 128       // max nodes per edge  (Binomial(8192,.005): mean 41.0, sd 6.4)

// ---------------- device scratch (static: no allocations allowed) ----------------
__device__ __align__(16) float g_v1[FIN];   // weight2 @ a[D:]
__device__ __align__(16) float g_v2[FIN];   // weight2 @ a2[:D]
__device__ __align__(16) float g_w3v[DD];   // weight3 @ a2[D:]
__device__ float g_c;                       // word_context . a[:D]
__device__ float g_xt[NN * DD];             // x @ weight
__device__ float g_s1[NN];                  // leaky(c + x.v1)
__device__ float g_n2[NN];                  // x.v2
__device__ int   g_node_cnt[NN];
__device__ int   g_node_idx[NN * CAPN];
__device__ __align__(16) int g_edge_cnt[MM];
__device__ int   g_edge_idx[MM * CAPE];
__device__ float g_edge[MM * DD];
__device__ float g_e2[MM];

// ---------------- helpers ----------------
__device__ __forceinline__ float blockReduceSum128(float v, float* red) {
    int lane = threadIdx.x & 31, wid = threadIdx.x >> 5;
    #pragma unroll
    for (int o = 16; o > 0; o >>= 1) v += __shfl_xor_sync(0xffffffffu, v, o);
    if (lane == 0) red[wid] = v;
    __syncthreads();
    float r = (red[0] + red[1]) + (red[2] + red[3]);
    __syncthreads();
    return r;
}
__device__ __forceinline__ float blockReduceMax128(float v, float* red) {
    int lane = threadIdx.x & 31, wid = threadIdx.x >> 5;
    #pragma unroll
    for (int o = 16; o > 0; o >>= 1) v = fmaxf(v, __shfl_xor_sync(0xffffffffu, v, o));
    if (lane == 0) red[wid] = v;
    __syncthreads();
    float r = fmaxf(fmaxf(red[0], red[1]), fmaxf(red[2], red[3]));
    __syncthreads();
    return r;
}

// ---------------- KZ0: zero edge counters + tiny precomputes ----------------------
__global__ void kz0(const float* __restrict__ W2, const float* __restrict__ W3,
                    const float* __restrict__ wc, const float* __restrict__ a,
                    const float* __restrict__ a2) {
    int b = blockIdx.x, t = threadIdx.x;
    if (b < 4) {
        int i = (b * 256 + t) * 4;
        *reinterpret_cast<int4*>(&g_edge_cnt[i]) = make_int4(0, 0, 0, 0);
        return;
    }
    // precompute block
    if (t < FIN) {
        float s1 = 0.f, s2 = 0.f;
        #pragma unroll 4
        for (int c = 0; c < DD; c++) {
            float w = W2[t * DD + c];
            s1 += w * a[DD + c];
            s2 += w * a2[c];
        }
        g_v1[t] = s1; g_v2[t] = s2;
    }
    if (t < DD) {
        float s = 0.f;
        #pragma unroll 4
        for (int c = 0; c < DD; c++) s += W3[t * DD + c] * a2[DD + c];
        g_w3v[t] = s;
    }
    if (t == 0) {
        float s = 0.f;
        for (int c = 0; c < DD; c++) s += wc[c] * a[c];
        g_c = s;
    }
}

// ---------------- GEMM body: xt = x @ weight, fp32x2 packed FMA -------------------
// 128 threads (one output column each), 16 rows per block.
__device__ __forceinline__ void k1_body(const float* __restrict__ x,
                                        const float* __restrict__ W,
                                        float2 (*xs)[9], int b1) {
    int t = threadIdx.x;
    int r0 = b1 * 16;

    for (int i = t; i < 16 * FIN; i += 128) {
        int r = i >> 8;          // 0..15
        int k = i & (FIN - 1);   // 0..255
        float v = x[(size_t)(r0 + r) * FIN + k];
        reinterpret_cast<float*>(&xs[k][r >> 1])[r & 1] = v;
    }
    __syncthreads();

    unsigned long long acc[8];
    #pragma unroll
    for (int p = 0; p < 8; p++) acc[p] = 0ull;

    const float* Wc = W + t;
    #pragma unroll 4
    for (int k = 0; k < FIN; k++) {
        float w = Wc[(size_t)k * DD];
        unsigned wu = __float_as_uint(w);
        unsigned long long bb;
        asm("mov.b64 %0, {%1, %1};" : "=l"(bb) : "r"(wu));
        #pragma unroll
        for (int p = 0; p < 8; p++) {
            unsigned long long xp = *reinterpret_cast<const unsigned long long*>(&xs[k][p]);
            asm("fma.rn.f32x2 %0, %1, %2, %0;" : "+l"(acc[p]) : "l"(xp), "l"(bb));
        }
    }

    #pragma unroll
    for (int p = 0; p < 8; p++) {
        unsigned lo, hi;
        asm("mov.b64 {%0, %1}, %2;" : "=r"(lo), "=r"(hi) : "l"(acc[p]));
        g_xt[(size_t)(r0 + 2 * p) * DD + t]     = __uint_as_float(lo);
        g_xt[(size_t)(r0 + 2 * p + 1) * DD + t] = __uint_as_float(hi);
    }
}

// ---------------- adj-scan warp body: s1/n2 + both sparse structures --------------
__device__ __forceinline__ void k2_warp(const float* __restrict__ x,
                                        const float* __restrict__ adj,
                                        int row, int lane) {
    // fused s1/n2 (formerly k1b)
    const float4* xr = reinterpret_cast<const float4*>(x + (size_t)row * FIN);
    const float4* v1 = reinterpret_cast<const float4*>(g_v1);
    const float4* v2 = reinterpret_cast<const float4*>(g_v2);
    float a1 = 0.f, a2v = 0.f;
    #pragma unroll
    for (int p = 0; p < 2; p++) {
        float4 xv = xr[lane + 32 * p];
        float4 u  = v1[lane + 32 * p];
        float4 vv = v2[lane + 32 * p];
        a1  += xv.x * u.x  + xv.y * u.y  + xv.z * u.z  + xv.w * u.w;
        a2v += xv.x * vv.x + xv.y * vv.y + xv.z * vv.z + xv.w * vv.w;
    }
    #pragma unroll
    for (int o = 16; o > 0; o >>= 1) {
        a1  += __shfl_xor_sync(0xffffffffu, a1, o);
        a2v += __shfl_xor_sync(0xffffffffu, a2v, o);
    }
    if (lane == 0) {
        float s = g_c + a1;
        g_s1[row] = (s > 0.f) ? s : 0.2f * s;
        g_n2[row] = a2v;
    }

    // adj scan: 16 iterations, 8 floats (2x float4) per lane per iteration
    const float4* r4 = reinterpret_cast<const float4*>(adj + (size_t)row * MM);
    int* nrow = g_node_idx + (size_t)row * CAPN;
    int base = 0;
    for (int c = 0; c < 16; c++) {
        float4 u0 = r4[c * 64 + lane * 2];
        float4 u1 = r4[c * 64 + lane * 2 + 1];
        unsigned mk = (unsigned)(u0.x > 0.f)        | ((unsigned)(u0.y > 0.f) << 1)
                    | ((unsigned)(u0.z > 0.f) << 2) | ((unsigned)(u0.w > 0.f) << 3)
                    | ((unsigned)(u1.x > 0.f) << 4) | ((unsigned)(u1.y > 0.f) << 5)
                    | ((unsigned)(u1.z > 0.f) << 6) | ((unsigned)(u1.w > 0.f) << 7);
        int cnt = __popc(mk);
        int pref = cnt;
        #pragma unroll
        for (int o = 1; o < 32; o <<= 1) {
            int n = __shfl_up_sync(0xffffffffu, pref, o);
            if (lane >= o) pref += n;
        }
        int total = __shfl_sync(0xffffffffu, pref, 31);
        int pos = base + pref - cnt;
        int m0 = c * 256 + lane * 8;
        #pragma unroll
        for (int q = 0; q < 8; q++) {
            if (mk & (1u << q)) {
                if (pos < CAPN) nrow[pos] = m0 + q;
                pos++;
                int m = m0 + q;
                int slot = atomicAdd(&g_edge_cnt[m], 1);
                if (slot < CAPE) g_edge_idx[(size_t)m * CAPE + slot] = row;
            }
        }
        base += total;
    }
    if (lane == 0) g_node_cnt[row] = base;
}

// ---------------- K-main: interleave GEMM blocks with adj-scan blocks -------------
// 2560 blocks x 128 threads: bid%5==0 -> GEMM (512 blocks), else adj scan (2048).
__global__ void __launch_bounds__(128) k_main(const float* __restrict__ x,
                                              const float* __restrict__ adj,
                                              const float* __restrict__ W) {
    __shared__ float2 xs[FIN][9];
    int bid = blockIdx.x;
    if (bid % 5 == 0) {
        k1_body(x, W, xs, bid / 5);
    } else {
        int b2 = bid - (bid / 5 + 1);           // 0..2047
        int row = b2 * 4 + (threadIdx.x >> 5);
        k2_warp(x, adj, row, threadIdx.x & 31);
    }
}

// ---------------- K23: sort edge list + per-edge softmax + aggregate + e2 ---------
__global__ void __launch_bounds__(128) k23() {
    __shared__ int   li[CAPE];
    __shared__ float w[CAPE];
    __shared__ float red[4];
    int m = blockIdx.x, t = threadIdx.x;
    int cnt = min(g_edge_cnt[m], CAPE);
    li[t] = (t < cnt) ? g_edge_idx[(size_t)m * CAPE + t] : 0x7fffffff;
    __syncthreads();
    // bitonic sort (determinism + gather locality)
    #pragma unroll 1
    for (int k = 2; k <= CAPE; k <<= 1) {
        #pragma unroll 1
        for (int j = k >> 1; j > 0; j >>= 1) {
            int ixj = t ^ j;
            if (ixj > t) {
                int a = li[t], b = li[ixj];
                bool asc = ((t & k) == 0);
                if ((a > b) == asc) { li[t] = b; li[ixj] = a; }
            }
            __syncthreads();
        }
    }
    // softmax over member nodes
    float sv = (t < cnt) ? g_s1[li[t]] : -INFINITY;
    float mx = blockReduceMax128(sv, red);
    float e = (t < cnt) ? __expf(sv - mx) : 0.f;
    w[t] = e;
    float sum = blockReduceSum128(e, red);
    __syncthreads();

    // gather: unroll x4 with independent accumulators (MLP=4)
    float acc0 = 0.f, acc1 = 0.f, acc2 = 0.f, acc3 = 0.f;
    int i = 0;
    #pragma unroll 1
    for (; i + 4 <= cnt; i += 4) {
        float p0 = g_xt[(size_t)li[i + 0] * DD + t];
        float p1 = g_xt[(size_t)li[i + 1] * DD + t];
        float p2 = g_xt[(size_t)li[i + 2] * DD + t];
        float p3 = g_xt[(size_t)li[i + 3] * DD + t];
        acc0 += w[i + 0] * p0; acc1 += w[i + 1] * p1;
        acc2 += w[i + 2] * p2; acc3 += w[i + 3] * p3;
    }
    for (; i < cnt; i++) acc0 += w[i] * g_xt[(size_t)li[i] * DD + t];
    float acc = (acc0 + acc1) + (acc2 + acc3);
    float val = (cnt > 0) ? acc / sum : 0.f;
    g_edge[(size_t)m * DD + t] = val;

    float e2 = blockReduceSum128(val * g_w3v[t], red);
    if (t == 0) g_e2[m] = e2;
}

// ---------------- K5: per-node softmax + aggregate edge; ELU ----------------------
__global__ void __launch_bounds__(128) k5(float* __restrict__ out) {
    __shared__ int   li[CAPN];
    __shared__ float w[CAPN];
    __shared__ float red[4];
    int j = blockIdx.x, t = threadIdx.x;
    int cnt = min(g_node_cnt[j], CAPN);
    if (t < cnt) li[t] = g_node_idx[(size_t)j * CAPN + t];
    __syncthreads();
    float n2 = g_n2[j];
    float sv = -INFINITY;
    if (t < cnt) {
        float s = g_e2[li[t]] + n2;
        sv = (s > 0.f) ? s : 0.2f * s;     // leaky on (e2_i + n2_j)
    }
    float mx = blockReduceMax128(sv, red);
    float e = (t < cnt) ? __expf(sv - mx) : 0.f;
    if (t < CAPN) w[t] = e;
    float sum = blockReduceSum128(e, red);
    __syncthreads();

    float acc0 = 0.f, acc1 = 0.f, acc2 = 0.f, acc3 = 0.f;
    int i = 0;
    #pragma unroll 1
    for (; i + 4 <= cnt; i += 4) {
        float p0 = g_edge[(size_t)li[i + 0] * DD + t];
        float p1 = g_edge[(size_t)li[i + 1] * DD + t];
        float p2 = g_edge[(size_t)li[i + 2] * DD + t];
        float p3 = g_edge[(size_t)li[i + 3] * DD + t];
        acc0 += w[i + 0] * p0; acc1 += w[i + 1] * p1;
        acc2 += w[i + 2] * p2; acc3 += w[i + 3] * p3;
    }
    for (; i < cnt; i++) acc0 += w[i] * g_edge[(size_t)li[i] * DD + t];
    float acc = (acc0 + acc1) + (acc2 + acc3);
    float val = (cnt > 0) ? acc / sum : 0.f;
    out[(size_t)j * DD + t] = (val > 0.f) ? val : (__expf(val) - 1.f);
}

// ---------------- launch ----------------------------------------------------------
extern "C" void kernel_launch(void* const* d_in, const int* in_sizes, int n_in,
                              void* d_out, int out_size) {
    const float* x   = (const float*)d_in[0];   // [8192,256]
    const float* adj = (const float*)d_in[1];   // [8192,4096]
    const float* W   = (const float*)d_in[2];   // [256,128]
    const float* W2  = (const float*)d_in[3];   // [256,128]
    const float* W3  = (const float*)d_in[4];   // [128,128]
    const float* wc  = (const float*)d_in[5];   // [1,128]
    const float* a   = (const float*)d_in[6];   // [256,1]
    const float* a2  = (const float*)d_in[7];   // [256,1]
    float* out = (float*)d_out;                 // [8192,128]

    kz0<<<5, 256>>>(W2, W3, wc, a, a2);
    k_main<<<2560, 128>>>(x, adj, W);
    k23<<<MM, 128>>>();
    k5<<<NN, 128>>>(out);
}

// round 3
// speedup vs baseline: 1.3456x; 1.1164x over previous
#include <cuda_runtime.h>
#include <cstdint>
#include <math.h>

// Problem sizes
#define NN   8192      // nodes
#define MM   4096      // hyperedges
#define FIN  256
#define DD   128
#define CAPN 64        // max edges per node  (Binomial(4096,.005): mean 20.5, sd 4.5)
#define CAPE 128       // max nodes per edge  (Binomial(8192,.005): mean 41.0, sd 6.4)

// ---------------- device scratch ----------------
__device__ __align__(16) float g_v1[FIN];
__device__ __align__(16) float g_v2[FIN];
__device__ __align__(16) float g_w3v[DD];
__device__ float g_c;
__device__ __align__(16) float g_xt[NN * DD];     // x @ weight
__device__ float g_s1[NN];                        // leaky(c + x.v1)
__device__ float g_n2[NN];                        // x.v2
__device__ int   g_node_cnt[NN];
__device__ int   g_node_idx[NN * CAPN];
__device__ __align__(16) int g_edge_cnt[MM];
__device__ int   g_edge_idx[MM * CAPE];
__device__ __align__(16) float g_edge[MM * DD];
__device__ float g_e2[MM];

// ---------------- KZ0: zero edge counters + tiny precomputes ---------------------
__global__ void kz0(const float* __restrict__ W2, const float* __restrict__ W3,
                    const float* __restrict__ wc, const float* __restrict__ a,
                    const float* __restrict__ a2) {
    int b = blockIdx.x, t = threadIdx.x;
    if (b < 4) {
        int i = (b * 256 + t) * 4;
        *reinterpret_cast<int4*>(&g_edge_cnt[i]) = make_int4(0, 0, 0, 0);
        return;
    }
    if (t < FIN) {
        float s1 = 0.f, s2 = 0.f;
        #pragma unroll 4
        for (int c = 0; c < DD; c++) {
            float w = W2[t * DD + c];
            s1 += w * a[DD + c];
            s2 += w * a2[c];
        }
        g_v1[t] = s1; g_v2[t] = s2;
    }
    if (t < DD) {
        float s = 0.f;
        #pragma unroll 4
        for (int c = 0; c < DD; c++) s += W3[t * DD + c] * a2[DD + c];
        g_w3v[t] = s;
    }
    if (t == 0) {
        float s = 0.f;
        for (int c = 0; c < DD; c++) s += wc[c] * a[c];
        g_c = s;
    }
}

// ---------------- GEMM body: xt = x @ weight, fp32x2 packed FMA ------------------
__device__ __forceinline__ void k1_body(const float* __restrict__ x,
                                        const float* __restrict__ W,
                                        float2 (*xs)[9], int b1) {
    int t = threadIdx.x;
    int r0 = b1 * 16;

    for (int i = t; i < 16 * FIN; i += 128) {
        int r = i >> 8;
        int k = i & (FIN - 1);
        float v = x[(r0 + r) * FIN + k];
        reinterpret_cast<float*>(&xs[k][r >> 1])[r & 1] = v;
    }
    __syncthreads();

    unsigned long long acc[8];
    #pragma unroll
    for (int p = 0; p < 8; p++) acc[p] = 0ull;

    const float* Wc = W + t;
    #pragma unroll 4
    for (int k = 0; k < FIN; k++) {
        float w = Wc[k * DD];
        unsigned wu = __float_as_uint(w);
        unsigned long long bb;
        asm("mov.b64 %0, {%1, %1};" : "=l"(bb) : "r"(wu));
        #pragma unroll
        for (int p = 0; p < 8; p++) {
            unsigned long long xp = *reinterpret_cast<const unsigned long long*>(&xs[k][p]);
            asm("fma.rn.f32x2 %0, %1, %2, %0;" : "+l"(acc[p]) : "l"(xp), "l"(bb));
        }
    }

    #pragma unroll
    for (int p = 0; p < 8; p++) {
        unsigned lo, hi;
        asm("mov.b64 {%0, %1}, %2;" : "=r"(lo), "=r"(hi) : "l"(acc[p]));
        g_xt[(r0 + 2 * p) * DD + t]     = __uint_as_float(lo);
        g_xt[(r0 + 2 * p + 1) * DD + t] = __uint_as_float(hi);
    }
}

// ---------------- adj-scan warp body: s1/n2 + both sparse structures -------------
__device__ __forceinline__ void k2_warp(const float* __restrict__ x,
                                        const float* __restrict__ adj,
                                        int row, int lane) {
    // s1/n2 mat-vec
    const float4* xr = reinterpret_cast<const float4*>(x + row * FIN);
    const float4* v1 = reinterpret_cast<const float4*>(g_v1);
    const float4* v2 = reinterpret_cast<const float4*>(g_v2);
    float a1 = 0.f, a2v = 0.f;
    #pragma unroll
    for (int p = 0; p < 2; p++) {
        float4 xv = xr[lane + 32 * p];
        float4 u  = v1[lane + 32 * p];
        float4 vv = v2[lane + 32 * p];
        a1  += xv.x * u.x  + xv.y * u.y  + xv.z * u.z  + xv.w * u.w;
        a2v += xv.x * vv.x + xv.y * vv.y + xv.z * vv.z + xv.w * vv.w;
    }
    #pragma unroll
    for (int o = 16; o > 0; o >>= 1) {
        a1  += __shfl_xor_sync(0xffffffffu, a1, o);
        a2v += __shfl_xor_sync(0xffffffffu, a2v, o);
    }
    if (lane == 0) {
        float s = g_c + a1;
        g_s1[row] = (s > 0.f) ? s : 0.2f * s;
        g_n2[row] = a2v;
    }

    // adj scan: 16 iterations, 8 floats (2x float4) per lane; ffs-based extraction
    const float4* r4 = reinterpret_cast<const float4*>(adj + (size_t)row * MM);
    int* nrow = g_node_idx + row * CAPN;
    int base = 0;
    #pragma unroll 1
    for (int c = 0; c < 16; c++) {
        float4 u0 = r4[c * 64 + lane * 2];
        float4 u1 = r4[c * 64 + lane * 2 + 1];
        unsigned mk = (unsigned)(u0.x > 0.f)        | ((unsigned)(u0.y > 0.f) << 1)
                    | ((unsigned)(u0.z > 0.f) << 2) | ((unsigned)(u0.w > 0.f) << 3)
                    | ((unsigned)(u1.x > 0.f) << 4) | ((unsigned)(u1.y > 0.f) << 5)
                    | ((unsigned)(u1.z > 0.f) << 6) | ((unsigned)(u1.w > 0.f) << 7);
        unsigned wm = __ballot_sync(0xffffffffu, mk != 0);
        while (wm) {
            int src = __ffs(wm) - 1; wm &= wm - 1;
            unsigned sm = __shfl_sync(0xffffffffu, mk, src);
            int mbase = c * 256 + src * 8;
            while (sm) {
                int q = __ffs(sm) - 1; sm &= sm - 1;
                if (lane == 0) {
                    int mcol = mbase + q;
                    if (base < CAPN) nrow[base] = mcol;
                    int slot = atomicAdd(&g_edge_cnt[mcol], 1);
                    if (slot < CAPE) g_edge_idx[mcol * CAPE + slot] = row;
                }
                base++;
            }
        }
    }
    if (lane == 0) g_node_cnt[row] = base;
}

// ---------------- K-main: interleave GEMM blocks with adj-scan blocks ------------
__global__ void __launch_bounds__(128) k_main(const float* __restrict__ x,
                                              const float* __restrict__ adj,
                                              const float* __restrict__ W) {
    __shared__ float2 xs[FIN][9];
    int bid = blockIdx.x;
    if (bid % 5 == 0) {
        k1_body(x, W, xs, bid / 5);
    } else {
        int b2 = bid - (bid / 5 + 1);           // 0..2047
        int row = b2 * 4 + (threadIdx.x >> 5);
        k2_warp(x, adj, row, threadIdx.x & 31);
    }
}

// ---------------- K3: warp-per-edge softmax + float4 gather + e2 -----------------
__global__ void __launch_bounds__(128) k3() {
    __shared__ int2 pw[4][CAPE];   // (xt float4-offset, weight bits)
    int warp = threadIdx.x >> 5, lane = threadIdx.x & 31;
    int m = blockIdx.x * 4 + warp;
    int cnt = min(g_edge_cnt[m], CAPE);
    const int* el = g_edge_idx + m * CAPE;

    float den = 0.f;
    #pragma unroll 1
    for (int k = lane; k < cnt; k += 32) {
        int idx = el[k];
        float e = __expf(g_s1[idx]);   // scores bounded: max-free softmax is safe
        den += e;
        pw[warp][k] = make_int2(idx * 32, __float_as_int(e));
    }
    #pragma unroll
    for (int o = 16; o > 0; o >>= 1) den += __shfl_xor_sync(0xffffffffu, den, o);
    __syncwarp();
    float inv = (cnt > 0) ? __frcp_rn(den) : 0.f;

    const float4* xt4 = reinterpret_cast<const float4*>(g_xt);
    float4 acc0 = make_float4(0.f, 0.f, 0.f, 0.f);
    float4 acc1 = make_float4(0.f, 0.f, 0.f, 0.f);
    float4 acc2 = make_float4(0.f, 0.f, 0.f, 0.f);
    float4 acc3 = make_float4(0.f, 0.f, 0.f, 0.f);
    int i = 0;
    #pragma unroll 1
    for (; i + 4 <= cnt; i += 4) {
        int2 a0 = pw[warp][i], a1 = pw[warp][i + 1];
        int2 a2 = pw[warp][i + 2], a3 = pw[warp][i + 3];
        float4 p0 = xt4[a0.x + lane];
        float4 p1 = xt4[a1.x + lane];
        float4 p2 = xt4[a2.x + lane];
        float4 p3 = xt4[a3.x + lane];
        float w0 = __int_as_float(a0.y), w1 = __int_as_float(a1.y);
        float w2 = __int_as_float(a2.y), w3 = __int_as_float(a3.y);
        acc0.x += w0 * p0.x; acc0.y += w0 * p0.y; acc0.z += w0 * p0.z; acc0.w += w0 * p0.w;
        acc1.x += w1 * p1.x; acc1.y += w1 * p1.y; acc1.z += w1 * p1.z; acc1.w += w1 * p1.w;
        acc2.x += w2 * p2.x; acc2.y += w2 * p2.y; acc2.z += w2 * p2.z; acc2.w += w2 * p2.w;
        acc3.x += w3 * p3.x; acc3.y += w3 * p3.y; acc3.z += w3 * p3.z; acc3.w += w3 * p3.w;
    }
    #pragma unroll 1
    for (; i < cnt; i++) {
        int2 a0 = pw[warp][i];
        float4 p0 = xt4[a0.x + lane];
        float w0 = __int_as_float(a0.y);
        acc0.x += w0 * p0.x; acc0.y += w0 * p0.y; acc0.z += w0 * p0.z; acc0.w += w0 * p0.w;
    }
    float4 r;
    r.x = ((acc0.x + acc1.x) + (acc2.x + acc3.x)) * inv;
    r.y = ((acc0.y + acc1.y) + (acc2.y + acc3.y)) * inv;
    r.z = ((acc0.z + acc1.z) + (acc2.z + acc3.z)) * inv;
    r.w = ((acc0.w + acc1.w) + (acc2.w + acc3.w)) * inv;
    reinterpret_cast<float4*>(g_edge)[m * 32 + lane] = r;

    float4 wv = reinterpret_cast<const float4*>(g_w3v)[lane];
    float part = r.x * wv.x + r.y * wv.y + r.z * wv.z + r.w * wv.w;
    #pragma unroll
    for (int o = 16; o > 0; o >>= 1) part += __shfl_xor_sync(0xffffffffu, part, o);
    if (lane == 0) g_e2[m] = part;
}

// ---------------- K5: warp-per-node softmax + float4 gather + ELU ----------------
__global__ void __launch_bounds__(128) k5(float* __restrict__ out) {
    __shared__ int2 pw[4][CAPN];
    int warp = threadIdx.x >> 5, lane = threadIdx.x & 31;
    int j = blockIdx.x * 4 + warp;
    int cnt = min(g_node_cnt[j], CAPN);
    const int* nl = g_node_idx + j * CAPN;
    float n2 = g_n2[j];

    float den = 0.f;
    #pragma unroll 1
    for (int k = lane; k < cnt; k += 32) {
        int idx = nl[k];
        float s = g_e2[idx] + n2;
        s = (s > 0.f) ? s : 0.2f * s;
        float e = __expf(s);
        den += e;
        pw[warp][k] = make_int2(idx * 32, __float_as_int(e));
    }
    #pragma unroll
    for (int o = 16; o > 0; o >>= 1) den += __shfl_xor_sync(0xffffffffu, den, o);
    __syncwarp();
    float inv = (cnt > 0) ? __frcp_rn(den) : 0.f;

    const float4* ed4 = reinterpret_cast<const float4*>(g_edge);
    float4 acc0 = make_float4(0.f, 0.f, 0.f, 0.f);
    float4 acc1 = make_float4(0.f, 0.f, 0.f, 0.f);
    float4 acc2 = make_float4(0.f, 0.f, 0.f, 0.f);
    float4 acc3 = make_float4(0.f, 0.f, 0.f, 0.f);
    int i = 0;
    #pragma unroll 1
    for (; i + 4 <= cnt; i += 4) {
        int2 a0 = pw[warp][i], a1 = pw[warp][i + 1];
        int2 a2 = pw[warp][i + 2], a3 = pw[warp][i + 3];
        float4 p0 = ed4[a0.x + lane];
        float4 p1 = ed4[a1.x + lane];
        float4 p2 = ed4[a2.x + lane];
        float4 p3 = ed4[a3.x + lane];
        float w0 = __int_as_float(a0.y), w1 = __int_as_float(a1.y);
        float w2 = __int_as_float(a2.y), w3 = __int_as_float(a3.y);
        acc0.x += w0 * p0.x; acc0.y += w0 * p0.y; acc0.z += w0 * p0.z; acc0.w += w0 * p0.w;
        acc1.x += w1 * p1.x; acc1.y += w1 * p1.y; acc1.z += w1 * p1.z; acc1.w += w1 * p1.w;
        acc2.x += w2 * p2.x; acc2.y += w2 * p2.y; acc2.z += w2 * p2.z; acc2.w += w2 * p2.w;
        acc3.x += w3 * p3.x; acc3.y += w3 * p3.y; acc3.z += w3 * p3.z; acc3.w += w3 * p3.w;
    }
    #pragma unroll 1
    for (; i < cnt; i++) {
        int2 a0 = pw[warp][i];
        float4 p0 = ed4[a0.x + lane];
        float w0 = __int_as_float(a0.y);
        acc0.x += w0 * p0.x; acc0.y += w0 * p0.y; acc0.z += w0 * p0.z; acc0.w += w0 * p0.w;
    }
    float4 r;
    r.x = ((acc0.x + acc1.x) + (acc2.x + acc3.x)) * inv;
    r.y = ((acc0.y + acc1.y) + (acc2.y + acc3.y)) * inv;
    r.z = ((acc0.z + acc1.z) + (acc2.z + acc3.z)) * inv;
    r.w = ((acc0.w + acc1.w) + (acc2.w + acc3.w)) * inv;
    r.x = (r.x > 0.f) ? r.x : (__expf(r.x) - 1.f);
    r.y = (r.y > 0.f) ? r.y : (__expf(r.y) - 1.f);
    r.z = (r.z > 0.f) ? r.z : (__expf(r.z) - 1.f);
    r.w = (r.w > 0.f) ? r.w : (__expf(r.w) - 1.f);
    reinterpret_cast<float4*>(out)[j * 32 + lane] = r;
}

// ---------------- launch ---------------------------------------------------------
extern "C" void kernel_launch(void* const* d_in, const int* in_sizes, int n_in,
                              void* d_out, int out_size) {
    const float* x   = (const float*)d_in[0];   // [8192,256]
    const float* adj = (const float*)d_in[1];   // [8192,4096]
    const float* W   = (const float*)d_in[2];   // [256,128]
    const float* W2  = (const float*)d_in[3];   // [256,128]
    const float* W3  = (const float*)d_in[4];   // [128,128]
    const float* wc  = (const float*)d_in[5];   // [1,128]
    const float* a   = (const float*)d_in[6];   // [256,1]
    const float* a2  = (const float*)d_in[7];   // [256,1]
    float* out = (float*)d_out;                 // [8192,128]

    kz0<<<5, 256>>>(W2, W3, wc, a, a2);
    k_main<<<2560, 128>>>(x, adj, W);
    k3<<<MM / 4, 128>>>();
    k5<<<NN / 4, 128>>>(out);
}

// round 4
// speedup vs baseline: 1.4134x; 1.0504x over previous
#include <cuda_runtime.h>
#include <cstdint>
#include <math.h>

// Problem sizes
#define NN   8192      // nodes
#define MM   4096      // hyperedges
#define FIN  256
#define DD   128
#define CAPN 64        // max edges per node  (Binomial(4096,.005): mean 20.5, sd 4.5)
#define CAPE 128       // max nodes per edge  (Binomial(8192,.005): mean 41.0, sd 6.4)

// ---------------- device scratch ----------------
__device__ __align__(16) float g_v1[FIN];
__device__ __align__(16) float g_v2[FIN];
__device__ __align__(16) float g_w3v[DD];
__device__ float g_c;
__device__ __align__(16) float g_xt[NN * DD];     // x @ weight
__device__ float g_s1[NN];                        // leaky(c + x.v1)
__device__ float g_n2[NN];                        // x.v2
__device__ int   g_node_cnt[NN];
__device__ int   g_node_idx[NN * CAPN];
__device__ __align__(16) int g_edge_cnt[MM];
__device__ int   g_edge_idx[MM * CAPE];
__device__ __align__(16) float g_edge[MM * DD];
__device__ float g_e2[MM];

// ---------------- KZ0: zero edge counters + tiny precomputes ---------------------
__global__ void kz0(const float* __restrict__ W2, const float* __restrict__ W3,
                    const float* __restrict__ wc, const float* __restrict__ a,
                    const float* __restrict__ a2) {
    int b = blockIdx.x, t = threadIdx.x;
    if (b < 4) {
        int i = (b * 256 + t) * 4;
        *reinterpret_cast<int4*>(&g_edge_cnt[i]) = make_int4(0, 0, 0, 0);
        return;
    }
    if (t < FIN) {
        float s1 = 0.f, s2 = 0.f;
        #pragma unroll 4
        for (int c = 0; c < DD; c++) {
            float w = W2[t * DD + c];
            s1 += w * a[DD + c];
            s2 += w * a2[c];
        }
        g_v1[t] = s1; g_v2[t] = s2;
    }
    if (t < DD) {
        float s = 0.f;
        #pragma unroll 4
        for (int c = 0; c < DD; c++) s += W3[t * DD + c] * a2[DD + c];
        g_w3v[t] = s;
    }
    if (t == 0) {
        float s = 0.f;
        for (int c = 0; c < DD; c++) s += wc[c] * a[c];
        g_c = s;
    }
}

// ---------------- GEMM body: xt = x @ weight + fused s1/n2 -----------------------
// 128 threads (one output column each), 16 rows per block.
__device__ __forceinline__ void k1_body(const float* __restrict__ x,
                                        const float* __restrict__ W,
                                        float2 (*xs)[9], int b1) {
    int t = threadIdx.x;
    int r0 = b1 * 16;

    for (int i = t; i < 16 * FIN; i += 128) {
        int r = i >> 8;
        int k = i & (FIN - 1);
        float v = x[(r0 + r) * FIN + k];
        reinterpret_cast<float*>(&xs[k][r >> 1])[r & 1] = v;
    }
    __syncthreads();

    unsigned long long acc[8];
    #pragma unroll
    for (int p = 0; p < 8; p++) acc[p] = 0ull;

    const float* Wc = W + t;
    #pragma unroll 4
    for (int k = 0; k < FIN; k++) {
        float w = Wc[k * DD];
        unsigned wu = __float_as_uint(w);
        unsigned long long bb;
        asm("mov.b64 %0, {%1, %1};" : "=l"(bb) : "r"(wu));
        #pragma unroll
        for (int p = 0; p < 8; p++) {
            unsigned long long xp = *reinterpret_cast<const unsigned long long*>(&xs[k][p]);
            asm("fma.rn.f32x2 %0, %1, %2, %0;" : "+l"(acc[p]) : "l"(xp), "l"(bb));
        }
    }

    #pragma unroll
    for (int p = 0; p < 8; p++) {
        unsigned lo, hi;
        asm("mov.b64 {%0, %1}, %2;" : "=r"(lo), "=r"(hi) : "l"(acc[p]));
        g_xt[(r0 + 2 * p) * DD + t]     = __uint_as_float(lo);
        g_xt[(r0 + 2 * p + 1) * DD + t] = __uint_as_float(hi);
    }

    // ---- fused s1/n2 for these 16 rows (x already in smem) ----
    {
        __shared__ float rb[2][4][16];
        int row = t & 15, seg = t >> 4;          // 8 segs x 32 k each
        float p1 = 0.f, p2 = 0.f;
        #pragma unroll 4
        for (int kk = 0; kk < 32; kk++) {
            int k = seg * 32 + kk;
            float xv = reinterpret_cast<const float*>(&xs[k][row >> 1])[row & 1];
            p1 += xv * g_v1[k];
            p2 += xv * g_v2[k];
        }
        p1 += __shfl_xor_sync(0xffffffffu, p1, 16);
        p2 += __shfl_xor_sync(0xffffffffu, p2, 16);
        int warp = t >> 5, lane = t & 31;
        if (lane < 16) { rb[0][warp][lane] = p1; rb[1][warp][lane] = p2; }
        __syncthreads();
        if (t < 16) {
            float s = g_c + ((rb[0][0][t] + rb[0][1][t]) + (rb[0][2][t] + rb[0][3][t]));
            g_s1[r0 + t] = (s > 0.f) ? s : 0.2f * s;
            g_n2[r0 + t] = (rb[1][0][t] + rb[1][1][t]) + (rb[1][2][t] + rb[1][3][t]);
        }
    }
}

// ---------------- adj-scan warp body: both sparse structures ---------------------
__device__ __forceinline__ void k2_warp(const float* __restrict__ adj,
                                        int row, int lane) {
    const float4* r4 = reinterpret_cast<const float4*>(adj + (size_t)row * MM);
    int* nrow = g_node_idx + row * CAPN;
    int base = 0;
    float4 u0 = __ldcs(&r4[lane * 2]);
    float4 u1 = __ldcs(&r4[lane * 2 + 1]);
    #pragma unroll 1
    for (int c = 0; c < 16; c++) {
        float4 n0, n1;
        if (c < 15) {                      // prefetch next chunk
            n0 = __ldcs(&r4[(c + 1) * 64 + lane * 2]);
            n1 = __ldcs(&r4[(c + 1) * 64 + lane * 2 + 1]);
        }
        unsigned mk = (unsigned)(u0.x > 0.f)        | ((unsigned)(u0.y > 0.f) << 1)
                    | ((unsigned)(u0.z > 0.f) << 2) | ((unsigned)(u0.w > 0.f) << 3)
                    | ((unsigned)(u1.x > 0.f) << 4) | ((unsigned)(u1.y > 0.f) << 5)
                    | ((unsigned)(u1.z > 0.f) << 6) | ((unsigned)(u1.w > 0.f) << 7);
        unsigned wm = __ballot_sync(0xffffffffu, mk != 0);
        while (wm) {
            int src = __ffs(wm) - 1; wm &= wm - 1;
            unsigned sm = __shfl_sync(0xffffffffu, mk, src);
            int mbase = c * 256 + src * 8;
            while (sm) {
                int q = __ffs(sm) - 1; sm &= sm - 1;
                if (lane == 0) {
                    int mcol = mbase + q;
                    if (base < CAPN) nrow[base] = mcol;
                    int slot = atomicAdd(&g_edge_cnt[mcol], 1);
                    if (slot < CAPE) g_edge_idx[mcol * CAPE + slot] = row;
                }
                base++;
            }
        }
        u0 = n0; u1 = n1;
    }
    if (lane == 0) g_node_cnt[row] = base;
}

// ---------------- K-main: interleave GEMM blocks with adj-scan blocks ------------
__global__ void __launch_bounds__(128) k_main(const float* __restrict__ x,
                                              const float* __restrict__ adj,
                                              const float* __restrict__ W) {
    __shared__ float2 xs[FIN][9];
    int bid = blockIdx.x;
    if (bid % 5 == 0) {
        k1_body(x, W, xs, bid / 5);
    } else {
        int b2 = bid - (bid / 5 + 1);           // 0..2047
        int row = b2 * 4 + (threadIdx.x >> 5);
        k2_warp(adj, row, threadIdx.x & 31);
    }
}

// ---------------- K3: block-per-edge; 4 warps split members ----------------------
__global__ void __launch_bounds__(128) k3() {
    __shared__ int   soff[CAPE];
    __shared__ float sw[CAPE];
    __shared__ float4 racc[4][32];
    __shared__ float rden[4];
    int t = threadIdx.x, warp = t >> 5, lane = t & 31;
    int m = blockIdx.x;
    int cnt = min(g_edge_cnt[m], CAPE);
    const int* el = g_edge_idx + m * CAPE;

    float den = 0.f;
    for (int k = t; k < cnt; k += 128) {
        int idx = el[k];
        float e = __expf(g_s1[idx]);     // scores bounded: max-free softmax safe
        soff[k] = idx * 32;
        sw[k] = e;
        den += e;
    }
    #pragma unroll
    for (int o = 16; o > 0; o >>= 1) den += __shfl_xor_sync(0xffffffffu, den, o);
    if (lane == 0) rden[warp] = den;
    __syncthreads();
    den = (rden[0] + rden[1]) + (rden[2] + rden[3]);
    float inv = (cnt > 0) ? __frcp_rn(den) : 0.f;

    const float4* xt4 = reinterpret_cast<const float4*>(g_xt);
    float4 A0 = make_float4(0.f, 0.f, 0.f, 0.f), A1 = A0, A2 = A0, A3 = A0;
    int i = warp;
    #pragma unroll 1
    for (; i + 12 < cnt; i += 16) {
        int o0 = soff[i], o1 = soff[i + 4], o2 = soff[i + 8], o3 = soff[i + 12];
        float w0 = sw[i], w1 = sw[i + 4], w2 = sw[i + 8], w3 = sw[i + 12];
        float4 p0 = xt4[o0 + lane], p1 = xt4[o1 + lane];
        float4 p2 = xt4[o2 + lane], p3 = xt4[o3 + lane];
        A0.x += w0 * p0.x; A0.y += w0 * p0.y; A0.z += w0 * p0.z; A0.w += w0 * p0.w;
        A1.x += w1 * p1.x; A1.y += w1 * p1.y; A1.z += w1 * p1.z; A1.w += w1 * p1.w;
        A2.x += w2 * p2.x; A2.y += w2 * p2.y; A2.z += w2 * p2.z; A2.w += w2 * p2.w;
        A3.x += w3 * p3.x; A3.y += w3 * p3.y; A3.z += w3 * p3.z; A3.w += w3 * p3.w;
    }
    #pragma unroll 1
    for (; i < cnt; i += 4) {
        float w0 = sw[i];
        float4 p0 = xt4[soff[i] + lane];
        A0.x += w0 * p0.x; A0.y += w0 * p0.y; A0.z += w0 * p0.z; A0.w += w0 * p0.w;
    }
    A0.x += (A1.x + A2.x) + A3.x; A0.y += (A1.y + A2.y) + A3.y;
    A0.z += (A1.z + A2.z) + A3.z; A0.w += (A1.w + A2.w) + A3.w;
    racc[warp][lane] = A0;
    __syncthreads();
    if (warp == 0) {
        float4 a0 = racc[0][lane], a1 = racc[1][lane], a2 = racc[2][lane], a3 = racc[3][lane];
        float4 r;
        r.x = ((a0.x + a1.x) + (a2.x + a3.x)) * inv;
        r.y = ((a0.y + a1.y) + (a2.y + a3.y)) * inv;
        r.z = ((a0.z + a1.z) + (a2.z + a3.z)) * inv;
        r.w = ((a0.w + a1.w) + (a2.w + a3.w)) * inv;
        reinterpret_cast<float4*>(g_edge)[m * 32 + lane] = r;
        float4 wv = reinterpret_cast<const float4*>(g_w3v)[lane];
        float part = r.x * wv.x + r.y * wv.y + r.z * wv.z + r.w * wv.w;
        #pragma unroll
        for (int o = 16; o > 0; o >>= 1) part += __shfl_xor_sync(0xffffffffu, part, o);
        if (lane == 0) g_e2[m] = part;
    }
}

// ---------------- K5: block-per-node; 4 warps split members; ELU -----------------
__global__ void __launch_bounds__(128) k5(float* __restrict__ out) {
    __shared__ int   soff[CAPN];
    __shared__ float sw[CAPN];
    __shared__ float4 racc[4][32];
    __shared__ float rden[4];
    int t = threadIdx.x, warp = t >> 5, lane = t & 31;
    int j = blockIdx.x;
    int cnt = min(g_node_cnt[j], CAPN);
    const int* nl = g_node_idx + j * CAPN;
    float n2 = g_n2[j];

    float den = 0.f;
    if (t < cnt) {
        int idx = nl[t];
        float s = g_e2[idx] + n2;
        s = (s > 0.f) ? s : 0.2f * s;
        float e = __expf(s);
        soff[t] = idx * 32;
        sw[t] = e;
        den = e;
    }
    #pragma unroll
    for (int o = 16; o > 0; o >>= 1) den += __shfl_xor_sync(0xffffffffu, den, o);
    if (lane == 0) rden[warp] = den;
    __syncthreads();
    den = (rden[0] + rden[1]) + (rden[2] + rden[3]);
    float inv = (cnt > 0) ? __frcp_rn(den) : 0.f;

    const float4* ed4 = reinterpret_cast<const float4*>(g_edge);
    float4 A0 = make_float4(0.f, 0.f, 0.f, 0.f), A1 = A0;
    int i = warp;
    #pragma unroll 1
    for (; i + 4 < cnt; i += 8) {
        float w0 = sw[i], w1 = sw[i + 4];
        float4 p0 = ed4[soff[i] + lane], p1 = ed4[soff[i + 4] + lane];
        A0.x += w0 * p0.x; A0.y += w0 * p0.y; A0.z += w0 * p0.z; A0.w += w0 * p0.w;
        A1.x += w1 * p1.x; A1.y += w1 * p1.y; A1.z += w1 * p1.z; A1.w += w1 * p1.w;
    }
    if (i < cnt) {
        float w0 = sw[i];
        float4 p0 = ed4[soff[i] + lane];
        A0.x += w0 * p0.x; A0.y += w0 * p0.y; A0.z += w0 * p0.z; A0.w += w0 * p0.w;
    }
    A0.x += A1.x; A0.y += A1.y; A0.z += A1.z; A0.w += A1.w;
    racc[warp][lane] = A0;
    __syncthreads();
    if (warp == 0) {
        float4 a0 = racc[0][lane], a1 = racc[1][lane], a2 = racc[2][lane], a3 = racc[3][lane];
        float4 r;
        r.x = ((a0.x + a1.x) + (a2.x + a3.x)) * inv;
        r.y = ((a0.y + a1.y) + (a2.y + a3.y)) * inv;
        r.z = ((a0.z + a1.z) + (a2.z + a3.z)) * inv;
        r.w = ((a0.w + a1.w) + (a2.w + a3.w)) * inv;
        r.x = (r.x > 0.f) ? r.x : (__expf(r.x) - 1.f);
        r.y = (r.y > 0.f) ? r.y : (__expf(r.y) - 1.f);
        r.z = (r.z > 0.f) ? r.z : (__expf(r.z) - 1.f);
        r.w = (r.w > 0.f) ? r.w : (__expf(r.w) - 1.f);
        reinterpret_cast<float4*>(out)[j * 32 + lane] = r;
    }
}

// ---------------- launch ---------------------------------------------------------
extern "C" void kernel_launch(void* const* d_in, const int* in_sizes, int n_in,
                              void* d_out, int out_size) {
    const float* x   = (const float*)d_in[0];   // [8192,256]
    const float* adj = (const float*)d_in[1];   // [8192,4096]
    const float* W   = (const float*)d_in[2];   // [256,128]
    const float* W2  = (const float*)d_in[3];   // [256,128]
    const float* W3  = (const float*)d_in[4];   // [128,128]
    const float* wc  = (const float*)d_in[5];   // [1,128]
    const float* a   = (const float*)d_in[6];   // [256,1]
    const float* a2  = (const float*)d_in[7];   // [256,1]
    float* out = (float*)d_out;                 // [8192,128]

    kz0<<<5, 256>>>(W2, W3, wc, a, a2);
    k_main<<<2560, 128>>>(x, adj, W);
    k3<<<MM, 128>>>();
    k5<<<NN, 128>>>(out);
}